// round 2
// baseline (speedup 1.0000x reference)
#include <cuda_runtime.h>
#include <math.h>

#define L 2048
#define DMOD 64
#define NH 4
#define DKV 16
#define NB 4
#define QT 32
#define KT 64
#define NEGV -1000000000.0f

// scratch (no allocs allowed): projected Q/K/V head-major [b][h][l][16], context [b][l][64]
__device__ float g_Qp[NB*NH*L*DKV];
__device__ float g_Kp[NB*NH*L*DKV];
__device__ float g_Vp[NB*NH*L*DKV];
__device__ float g_ctx[NB*L*DMOD];

// ---------------------------------------------------------------------------
// Projection: [B*L,64] @ [64,64] for Q,K,V -> head-major scratch
// ---------------------------------------------------------------------------
__global__ void __launch_bounds__(256) proj_kernel(
    const float* __restrict__ inQ, const float* __restrict__ inK,
    const float* __restrict__ inV, const float* __restrict__ WQ,
    const float* __restrict__ WK, const float* __restrict__ WV)
{
    __shared__ float wq[DMOD*DMOD], wk[DMOD*DMOD], wv[DMOD*DMOD];
    __shared__ float sq[4][DMOD], sk[4][DMOD], sv[4][DMOD];
    for (int i = threadIdx.x; i < DMOD*DMOD; i += 256) {
        wq[i] = WQ[i]; wk[i] = WK[i]; wv[i] = WV[i];
    }
    __syncthreads();
    const int c    = threadIdx.x & 63;
    const int rsub = threadIdx.x >> 6;
    const int row0 = blockIdx.x * 64;
    for (int r = 0; r < 64; r += 4) {
        const int row = row0 + r + rsub;
        sq[rsub][c] = inQ[row*DMOD + c];
        sk[rsub][c] = inK[row*DMOD + c];
        sv[rsub][c] = inV[row*DMOD + c];
        __syncthreads();
        float aq = 0.f, ak = 0.f, av = 0.f;
        #pragma unroll
        for (int e = 0; e < DMOD; e++) {
            const float* wqe = &wq[e*DMOD + c];
            aq = fmaf(sq[rsub][e], wq[e*DMOD + c], aq);
            ak = fmaf(sk[rsub][e], wk[e*DMOD + c], ak);
            av = fmaf(sv[rsub][e], wv[e*DMOD + c], av);
            (void)wqe;
        }
        const int b = row >> 11, l = row & (L-1);
        const int h = c >> 4,   d = c & 15;
        const int idx = (((b*NH + h)*L) + l)*DKV + d;
        g_Qp[idx] = aq; g_Kp[idx] = ak; g_Vp[idx] = av;
        __syncthreads();
    }
}

// ---------------------------------------------------------------------------
// Attention: per block = (bh, 32-query tile). Online softmax, streams raw
// scores to gmem exactly once. Thread t -> (q = t>>3, lane j = t&7 owning
// keys j, j+8, ..., j+56 of each 64-key tile). acc[16] per-thread partial,
// reduced across the 8 lanes at the end via shfl.
// ---------------------------------------------------------------------------
__global__ void __launch_bounds__(256) attn_kernel(
    const float* __restrict__ res_att,
    const unsigned char* __restrict__ mask,
    float* __restrict__ scores)
{
    const int bh = blockIdx.y;          // b*NH + h
    const int b  = bh >> 2;
    const int q0 = blockIdx.x * QT;
    const int t  = threadIdx.x;
    const int q  = t >> 3;              // local query 0..31
    const int j  = t & 7;
    const int qg = q0 + q;

    __shared__ float sK[KT][20];        // stride 20: conflict-free LDS.128
    __shared__ float sV[KT][20];

    // query row into registers (broadcast across 8 lanes via L1)
    float qr[DKV];
    {
        const float* Qrow = g_Qp + ((size_t)bh*L + qg)*DKV;
        #pragma unroll
        for (int e = 0; e < DKV; e += 4) {
            float4 v = *(const float4*)(Qrow + e);
            qr[e] = v.x; qr[e+1] = v.y; qr[e+2] = v.z; qr[e+3] = v.w;
        }
    }

    const float*         resrow = res_att + ((size_t)bh*L + qg)*L;
    const unsigned char* mrow   = mask    + ((size_t)b *L + qg)*L;
    float*               srow   = scores  + ((size_t)bh*L + qg)*L;

    float m = -INFINITY, lsum = 0.f;
    float acc[DKV];
    #pragma unroll
    for (int d = 0; d < DKV; d++) acc[d] = 0.f;

    for (int kt = 0; kt < L; kt += KT) {
        __syncthreads();
        {   // stage K,V tile: 64 rows x 16 floats, one float4 per thread
            const int kk = t >> 2;
            const int e0 = (t & 3) * 4;
            const size_t g = ((size_t)bh*L + kt + kk)*DKV + e0;
            float4 k4 = *(const float4*)(g_Kp + g);
            sK[kk][e0] = k4.x; sK[kk][e0+1] = k4.y; sK[kk][e0+2] = k4.z; sK[kk][e0+3] = k4.w;
            float4 v4 = *(const float4*)(g_Vp + g);
            sV[kk][e0] = v4.x; sV[kk][e0+1] = v4.y; sV[kk][e0+2] = v4.z; sV[kk][e0+3] = v4.w;
        }
        __syncthreads();

        float s[8];
        float mloc = -INFINITY;
        #pragma unroll
        for (int i = 0; i < 8; i++) {
            const int kl = i*8 + j;
            float a = 0.f;
            #pragma unroll
            for (int e = 0; e < DKV; e += 4) {
                float4 k4 = *(const float4*)&sK[kl][e];
                a = fmaf(qr[e],   k4.x, a);
                a = fmaf(qr[e+1], k4.y, a);
                a = fmaf(qr[e+2], k4.z, a);
                a = fmaf(qr[e+3], k4.w, a);
            }
            float sv = fmaf(a, 0.25f, resrow[kt + kl]);
            if (mrow[kt + kl]) sv = NEGV;
            srow[kt + kl] = sv;                 // raw masked score output
            s[i] = sv;
            mloc = fmaxf(mloc, sv);
        }
        // reduce max across the 8 lanes sharing q
        #pragma unroll
        for (int w = 4; w >= 1; w >>= 1)
            mloc = fmaxf(mloc, __shfl_xor_sync(0xffffffffu, mloc, w));
        const float mnew = fmaxf(m, mloc);
        const float corr = __expf(m - mnew);

        float p[8];
        float psum = 0.f;
        #pragma unroll
        for (int i = 0; i < 8; i++) { p[i] = __expf(s[i] - mnew); psum += p[i]; }
        #pragma unroll
        for (int w = 4; w >= 1; w >>= 1)
            psum += __shfl_xor_sync(0xffffffffu, psum, w);
        lsum = fmaf(lsum, corr, psum);
        m = mnew;

        #pragma unroll
        for (int d = 0; d < DKV; d++) acc[d] *= corr;
        #pragma unroll
        for (int i = 0; i < 8; i++) {
            const int kl = i*8 + j;
            const float pi = p[i];
            #pragma unroll
            for (int d = 0; d < DKV; d += 4) {
                float4 v4 = *(const float4*)&sV[kl][d];
                acc[d]   = fmaf(pi, v4.x, acc[d]);
                acc[d+1] = fmaf(pi, v4.y, acc[d+1]);
                acc[d+2] = fmaf(pi, v4.z, acc[d+2]);
                acc[d+3] = fmaf(pi, v4.w, acc[d+3]);
            }
        }
    }

    // reduce acc across the 8 lanes of the q-group
    #pragma unroll
    for (int d = 0; d < DKV; d++) {
        #pragma unroll
        for (int w = 4; w >= 1; w >>= 1)
            acc[d] += __shfl_xor_sync(0xffffffffu, acc[d], w);
    }
    const float inv_l = 1.f / lsum;
    const int h = bh & 3;
    float* crow = g_ctx + ((size_t)b*L + qg)*DMOD + h*DKV;
    crow[2*j]     = acc[2*j]     * inv_l;
    crow[2*j + 1] = acc[2*j + 1] * inv_l;
}

// ---------------------------------------------------------------------------
// Epilogue: out = LayerNorm(ctx @ W_fc + input_Q). 256 threads = 4 rows.
// ---------------------------------------------------------------------------
__global__ void __launch_bounds__(256) epilogue_kernel(
    const float* __restrict__ inQ, const float* __restrict__ Wfc,
    float* __restrict__ out)
{
    __shared__ float w[DMOD*DMOD];
    __shared__ float sx[4][DMOD];
    __shared__ float red[4][2][2];
    for (int i = threadIdx.x; i < DMOD*DMOD; i += 256) w[i] = Wfc[i];

    const int c    = threadIdx.x & 63;
    const int rsub = threadIdx.x >> 6;
    const int row  = blockIdx.x * 4 + rsub;

    sx[rsub][c] = g_ctx[row*DMOD + c];
    __syncthreads();

    float y = inQ[row*DMOD + c];
    #pragma unroll
    for (int e = 0; e < DMOD; e++)
        y = fmaf(sx[rsub][e], w[e*DMOD + c], y);

    float s1 = y, s2 = y * y;
    #pragma unroll
    for (int wd = 16; wd >= 1; wd >>= 1) {
        s1 += __shfl_xor_sync(0xffffffffu, s1, wd);
        s2 += __shfl_xor_sync(0xffffffffu, s2, wd);
    }
    const int wsub = (threadIdx.x >> 5) & 1;
    if ((threadIdx.x & 31) == 0) { red[rsub][wsub][0] = s1; red[rsub][wsub][1] = s2; }
    __syncthreads();
    const float S1 = red[rsub][0][0] + red[rsub][1][0];
    const float S2 = red[rsub][0][1] + red[rsub][1][1];
    const float mu  = S1 * (1.f/64.f);
    const float var = S2 * (1.f/64.f) - mu*mu;
    out[row*DMOD + c] = (y - mu) * rsqrtf(var + 1e-5f);
}

// ---------------------------------------------------------------------------
extern "C" void kernel_launch(void* const* d_in, const int* in_sizes, int n_in,
                              void* d_out, int out_size)
{
    const float*         inQ  = (const float*)d_in[0];
    const float*         inK  = (const float*)d_in[1];
    const float*         inV  = (const float*)d_in[2];
    const unsigned char* mask = (const unsigned char*)d_in[3];
    const float*         res  = (const float*)d_in[4];
    const float*         WQ   = (const float*)d_in[5];
    const float*         WK   = (const float*)d_in[6];
    const float*         WV   = (const float*)d_in[7];
    const float*         Wfc  = (const float*)d_in[8];

    float* out    = (float*)d_out;
    float* scores = out + (size_t)NB * L * DMOD;   // tuple order: (out, scores)

    proj_kernel<<<(NB*L)/64, 256>>>(inQ, inK, inV, WQ, WK, WV);
    attn_kernel<<<dim3(L/QT, NB*NH), 256>>>(res, mask, scores);
    epilogue_kernel<<<(NB*L)/4, 256>>>(inQ, Wfc, out);
}

// round 3
// speedup vs baseline: 1.6234x; 1.6234x over previous
#include <cuda_runtime.h>
#include <math.h>

#define L 2048
#define DMOD 64
#define NH 4
#define DKV 16
#define NB 4
#define NEGV -1000000000.0f

typedef unsigned long long u64;

// scratch: projected Q/K/V head-major [b][h][l][16], context [b][l][64]
__device__ float g_Qp[NB*NH*L*DKV];
__device__ float g_Kp[NB*NH*L*DKV];
__device__ float g_Vp[NB*NH*L*DKV];
__device__ float g_ctx[NB*L*DMOD];

// ---- packed f32x2 helpers -------------------------------------------------
__device__ __forceinline__ u64 ffma2(u64 a, u64 b, u64 c) {
    u64 d; asm("fma.rn.f32x2 %0, %1, %2, %3;" : "=l"(d) : "l"(a), "l"(b), "l"(c));
    return d;
}
__device__ __forceinline__ u64 fmul2(u64 a, u64 b) {
    u64 d; asm("mul.rn.f32x2 %0, %1, %2;" : "=l"(d) : "l"(a), "l"(b));
    return d;
}
__device__ __forceinline__ u64 pack2(float x, float y) {
    u64 r; asm("mov.b64 %0, {%1, %2};" : "=l"(r) : "f"(x), "f"(y));
    return r;
}
__device__ __forceinline__ float2 unpack2(u64 a) {
    float2 v; asm("mov.b64 {%0, %1}, %2;" : "=f"(v.x), "=f"(v.y) : "l"(a));
    return v;
}

// ---------------------------------------------------------------------------
// Projection: 1024 blocks x 8 rows. Thread (cp = t&31 -> cols 2cp,2cp+1,
// rsub = t>>5 -> row). Weights streamed as coalesced u64 LDG (L2-resident),
// inputs broadcast from smem, FFMA2 accumulators, u64 stores.
// ---------------------------------------------------------------------------
__global__ void __launch_bounds__(256) proj_kernel(
    const float* __restrict__ inQ, const float* __restrict__ inK,
    const float* __restrict__ inV, const float* __restrict__ WQ,
    const float* __restrict__ WK, const float* __restrict__ WV)
{
    __shared__ float sq[8][DMOD], sk[8][DMOD], sv[8][DMOD];
    const int t = threadIdx.x;
    const int row0 = blockIdx.x * 8;
    #pragma unroll
    for (int idx = t; idx < 8*DMOD; idx += 256) {
        const int r = idx >> 6, c = idx & 63;
        const size_t g = (size_t)(row0 + r) * DMOD + c;
        sq[r][c] = inQ[g]; sk[r][c] = inK[g]; sv[r][c] = inV[g];
    }
    __syncthreads();

    const int cp = t & 31, rsub = t >> 5;
    const u64* __restrict__ wq2 = (const u64*)WQ;
    const u64* __restrict__ wk2 = (const u64*)WK;
    const u64* __restrict__ wv2 = (const u64*)WV;

    u64 aq = 0ull, ak = 0ull, av = 0ull;
    #pragma unroll 16
    for (int e = 0; e < DMOD; e++) {
        const float xq = sq[rsub][e], xk = sk[rsub][e], xv = sv[rsub][e];
        aq = ffma2(pack2(xq, xq), __ldg(&wq2[e*32 + cp]), aq);
        ak = ffma2(pack2(xk, xk), __ldg(&wk2[e*32 + cp]), ak);
        av = ffma2(pack2(xv, xv), __ldg(&wv2[e*32 + cp]), av);
    }

    const int row = row0 + rsub;
    const int b = row >> 11, l = row & (L-1);
    const int c0 = cp * 2;
    const int h = c0 >> 4, d = c0 & 15;
    const size_t o = (((size_t)b*NH + h)*L + l)*DKV + d;
    *(u64*)&g_Qp[o] = aq;
    *(u64*)&g_Kp[o] = ak;
    *(u64*)&g_Vp[o] = av;
}

// ---------------------------------------------------------------------------
// Attention: block = 128 thr = (bh, 64-query tile). Thread owns 4 queries
// (g = t>>3 in [0,16), queries qg0..qg0+3) x 8 strided keys (j = t&7).
// K/V tiles (64 keys) staged in smem, read as ulonglong2 -> pre-packed pairs
// for FFMA2. Online softmax; raw masked scores streamed to gmem once.
// ---------------------------------------------------------------------------
__global__ void __launch_bounds__(128, 2) attn_kernel(
    const float* __restrict__ res_att,
    const unsigned char* __restrict__ mask,
    float* __restrict__ scores)
{
    const int bh = blockIdx.y;
    const int b  = bh >> 2, h = bh & 3;
    const int q0 = blockIdx.x * 64;
    const int t  = threadIdx.x;
    const int j  = t & 7;
    const int g  = t >> 3;
    const int qg0 = q0 + g * 4;

    __shared__ float sK[64][20];   // stride 20 floats: conflict-free, 8B-aligned rows
    __shared__ float sV[64][20];

    // 4 query rows -> packed register pairs
    u64 qp[4][8];
    #pragma unroll
    for (int q = 0; q < 4; q++) {
        const ulonglong2* Qrow = (const ulonglong2*)(g_Qp + ((size_t)bh*L + qg0 + q)*DKV);
        #pragma unroll
        for (int e = 0; e < 4; e++) {
            ulonglong2 v = Qrow[e];
            qp[q][2*e] = v.x; qp[q][2*e+1] = v.y;
        }
    }

    const float*         res0 = res_att + ((size_t)bh*L + qg0)*L;
    const unsigned char* msk0 = mask    + ((size_t)b *L + qg0)*L;
    float*               scr0 = scores  + ((size_t)bh*L + qg0)*L;

    float m[4], lsum[4];
    u64 acc[4][8];
    #pragma unroll
    for (int q = 0; q < 4; q++) {
        m[q] = -INFINITY; lsum[q] = 0.f;
        #pragma unroll
        for (int d8 = 0; d8 < 8; d8++) acc[q][d8] = 0ull;
    }

    for (int kt = 0; kt < L; kt += 64) {
        __syncthreads();
        // stage 64 keys x 16 floats of K and V: 2 float4 per thread per array
        #pragma unroll
        for (int s2 = 0; s2 < 2; s2++) {
            const int idx = t + s2*128;
            const int kk = idx >> 2, e0 = (idx & 3) * 4;
            const size_t gg = ((size_t)bh*L + kt + kk)*DKV + e0;
            *(float4*)&sK[kk][e0] = *(const float4*)(g_Kp + gg);
            *(float4*)&sV[kk][e0] = *(const float4*)(g_Vp + gg);
        }
        __syncthreads();

        // --- QK^T + res + mask, stream scores ---
        float s[4][8];
        #pragma unroll
        for (int i = 0; i < 8; i++) {
            const int kl = i*8 + j;
            const ulonglong2* kp = (const ulonglong2*)&sK[kl][0];
            const ulonglong2 k01 = kp[0], k23 = kp[1], k45 = kp[2], k67 = kp[3];
            #pragma unroll
            for (int q = 0; q < 4; q++) {
                u64 a2 = 0ull;
                a2 = ffma2(qp[q][0], k01.x, a2);
                a2 = ffma2(qp[q][1], k01.y, a2);
                a2 = ffma2(qp[q][2], k23.x, a2);
                a2 = ffma2(qp[q][3], k23.y, a2);
                a2 = ffma2(qp[q][4], k45.x, a2);
                a2 = ffma2(qp[q][5], k45.y, a2);
                a2 = ffma2(qp[q][6], k67.x, a2);
                a2 = ffma2(qp[q][7], k67.y, a2);
                const float2 u = unpack2(a2);
                float sv = fmaf(u.x + u.y, 0.25f, res0[(size_t)q*L + kt + kl]);
                if (msk0[(size_t)q*L + kt + kl]) sv = NEGV;
                scr0[(size_t)q*L + kt + kl] = sv;
                s[q][i] = sv;
            }
        }

        // --- online softmax (per query, reduce across the 8 j-lanes) ---
        #pragma unroll
        for (int q = 0; q < 4; q++) {
            float ml = s[q][0];
            #pragma unroll
            for (int i = 1; i < 8; i++) ml = fmaxf(ml, s[q][i]);
            #pragma unroll
            for (int w = 4; w >= 1; w >>= 1)
                ml = fmaxf(ml, __shfl_xor_sync(0xffffffffu, ml, w));
            const float mn = fmaxf(m[q], ml);
            const float c  = __expf(m[q] - mn);
            float ps = 0.f;
            #pragma unroll
            for (int i = 0; i < 8; i++) { s[q][i] = __expf(s[q][i] - mn); ps += s[q][i]; }
            #pragma unroll
            for (int w = 4; w >= 1; w >>= 1)
                ps += __shfl_xor_sync(0xffffffffu, ps, w);
            lsum[q] = fmaf(lsum[q], c, ps);
            m[q] = mn;
            const u64 c2 = pack2(c, c);
            #pragma unroll
            for (int d8 = 0; d8 < 8; d8++) acc[q][d8] = fmul2(acc[q][d8], c2);
        }

        // --- P @ V (s[] now holds p) ---
        #pragma unroll
        for (int i = 0; i < 8; i++) {
            const int kl = i*8 + j;
            const ulonglong2* vp = (const ulonglong2*)&sV[kl][0];
            const ulonglong2 v01 = vp[0], v23 = vp[1], v45 = vp[2], v67 = vp[3];
            #pragma unroll
            for (int q = 0; q < 4; q++) {
                const u64 p2 = pack2(s[q][i], s[q][i]);
                acc[q][0] = ffma2(p2, v01.x, acc[q][0]);
                acc[q][1] = ffma2(p2, v01.y, acc[q][1]);
                acc[q][2] = ffma2(p2, v23.x, acc[q][2]);
                acc[q][3] = ffma2(p2, v23.y, acc[q][3]);
                acc[q][4] = ffma2(p2, v45.x, acc[q][4]);
                acc[q][5] = ffma2(p2, v45.y, acc[q][5]);
                acc[q][6] = ffma2(p2, v67.x, acc[q][6]);
                acc[q][7] = ffma2(p2, v67.y, acc[q][7]);
            }
        }
    }

    // final: reduce acc across the 8 lanes, lane j==0 writes the row
    #pragma unroll
    for (int q = 0; q < 4; q++) {
        float vals[16];
        #pragma unroll
        for (int d8 = 0; d8 < 8; d8++) {
            const float2 u = unpack2(acc[q][d8]);
            vals[2*d8] = u.x; vals[2*d8+1] = u.y;
        }
        #pragma unroll
        for (int d = 0; d < 16; d++) {
            #pragma unroll
            for (int w = 4; w >= 1; w >>= 1)
                vals[d] += __shfl_xor_sync(0xffffffffu, vals[d], w);
        }
        if (j == 0) {
            const float inv = 1.f / lsum[q];
            float* crow = g_ctx + ((size_t)b*L + qg0 + q)*DMOD + h*DKV;
            #pragma unroll
            for (int d8 = 0; d8 < 4; d8++) {
                float4 o;
                o.x = vals[4*d8+0]*inv; o.y = vals[4*d8+1]*inv;
                o.z = vals[4*d8+2]*inv; o.w = vals[4*d8+3]*inv;
                *(float4*)&crow[4*d8] = o;
            }
        }
    }
}

// ---------------------------------------------------------------------------
// Epilogue: out = LayerNorm(ctx @ W_fc + input_Q). 256 threads = 4 rows.
// ---------------------------------------------------------------------------
__global__ void __launch_bounds__(256) epilogue_kernel(
    const float* __restrict__ inQ, const float* __restrict__ Wfc,
    float* __restrict__ out)
{
    __shared__ float w[DMOD*DMOD];
    __shared__ float sx[4][DMOD];
    __shared__ float red[4][2][2];
    for (int i = threadIdx.x; i < DMOD*DMOD; i += 256) w[i] = Wfc[i];

    const int c    = threadIdx.x & 63;
    const int rsub = threadIdx.x >> 6;
    const int row  = blockIdx.x * 4 + rsub;

    sx[rsub][c] = g_ctx[row*DMOD + c];
    __syncthreads();

    float y = inQ[row*DMOD + c];
    #pragma unroll
    for (int e = 0; e < DMOD; e++)
        y = fmaf(sx[rsub][e], w[e*DMOD + c], y);

    float s1 = y, s2 = y * y;
    #pragma unroll
    for (int wd = 16; wd >= 1; wd >>= 1) {
        s1 += __shfl_xor_sync(0xffffffffu, s1, wd);
        s2 += __shfl_xor_sync(0xffffffffu, s2, wd);
    }
    const int wsub = (threadIdx.x >> 5) & 1;
    if ((threadIdx.x & 31) == 0) { red[rsub][wsub][0] = s1; red[rsub][wsub][1] = s2; }
    __syncthreads();
    const float S1 = red[rsub][0][0] + red[rsub][1][0];
    const float S2 = red[rsub][0][1] + red[rsub][1][1];
    const float mu  = S1 * (1.f/64.f);
    const float var = S2 * (1.f/64.f) - mu*mu;
    out[row*DMOD + c] = (y - mu) * rsqrtf(var + 1e-5f);
}

// ---------------------------------------------------------------------------
extern "C" void kernel_launch(void* const* d_in, const int* in_sizes, int n_in,
                              void* d_out, int out_size)
{
    const float*         inQ  = (const float*)d_in[0];
    const float*         inK  = (const float*)d_in[1];
    const float*         inV  = (const float*)d_in[2];
    const unsigned char* mask = (const unsigned char*)d_in[3];
    const float*         res  = (const float*)d_in[4];
    const float*         WQ   = (const float*)d_in[5];
    const float*         WK   = (const float*)d_in[6];
    const float*         WV   = (const float*)d_in[7];
    const float*         Wfc  = (const float*)d_in[8];

    float* out    = (float*)d_out;
    float* scores = out + (size_t)NB * L * DMOD;   // tuple order: (out, scores)

    proj_kernel<<<(NB*L)/8, 256>>>(inQ, inK, inV, WQ, WK, WV);
    attn_kernel<<<dim3(L/64, NB*NH), 128>>>(res, mask, scores);
    epilogue_kernel<<<(NB*L)/4, 256>>>(inQ, Wfc, out);
}